// round 12
// baseline (speedup 1.0000x reference)
#include <cuda_runtime.h>
#include <stdint.h>
#include <math.h>

// HighPassFilter: order-2 IIR biquad, 256 sequences of T=65536 float32.
// R12: halve the serialized round count. Each iteration now processes 64
// samples (two 32-sample subtiles, same validated swizzle math per subtile),
// WARM=64 (rel_err 5.9e-7 validated in R10), NT 11->5, NBUF=2 (8KB buffers;
// prefetch lead = one full iteration ~1000 cycles > loaded DRAM latency).
// R11 evidence: nothing saturated (DRAM 52%, L1 39%, issue 24%) -> the cost
// is per-round serialization (wait/LDS/chain/sync/store/sync x11); fewer,
// fatter rounds amortize it.

#define T_LEN   65536
#define CHUNK   256     // samples per lane
#define WARM    64      // warm-up samples (validated numerically in R10)
#define JT2     64      // samples per iteration (2 subtiles of 32)
#define NT2     ((CHUNK + WARM) / JT2)   // 5 iterations per warp
#define BLOCK_WARPS 2

#define SUBBYTES  4096              // 32 rows x 128B, one subtile
#define BUFBYTES  (2 * SUBBYTES)    // 8KB per ring buffer

__device__ __forceinline__ void cp_async16(uint32_t dst_smem, const float* src, int src_size)
{
    asm volatile("cp.async.cg.shared.global [%0], [%1], 16, %2;\n"
                 :: "r"(dst_smem), "l"(src), "r"(src_size));
}

__global__ __launch_bounds__(BLOCK_WARPS * 32, 1)
void biquad_hp_kernel(const float* __restrict__ x, float* __restrict__ y,
                      float b0, float b1, float b2, float na1, float na2)
{
    // [warp][ringbuf][subtile][row=chunk][col], swizzled per 32x32 subtile
    __shared__ __align__(16) float tile[BLOCK_WARPS][2][2][32][32];

    const int w    = threadIdx.x >> 5;
    const int lane = threadIdx.x & 31;
    const int g    = lane >> 3;   // chunk subgroup (0..3)
    const int m    = lane & 7;    // 16B slot within a 32-sample row (0..7)

    // 8 warps per sequence, each warp owns 32 contiguous chunks = 8192 samples
    const int gw   = blockIdx.x * BLOCK_WARPS + w;
    const int seq  = gw >> 3;
    const int wseq = gw & 7;

    const long long seqbase = (long long)seq * T_LEN;
    const float* xs = x + seqbase;
    float*       ys = y + seqbase;
    const int warpbase = wseq * (32 * CHUNK);
    const int slotbase = warpbase + g * CHUNK + 4 * m;   // chunk 4it+g, +4m

    uint32_t ringbase;
    asm("{ .reg .u64 t; cvta.to.shared.u64 t, %1; cvt.u32.u64 %0, t; }"
        : "=r"(ringbase) : "l"(&tile[w][0][0][0][0]));

    // cp.async dst within a subtile: row r=4it+g, logical quad m -> phys m^(r&7)
    //   byte = it*512 + g*128 + ((m^g)*16 ^ (it&1 ? 64 : 0))
    const uint32_t off0 = (uint32_t)g * 128u + (uint32_t)((m ^ g) << 4);
    const uint32_t off1 = off0 ^ 64u;
    // store-side float index within a subtile, per it
    const int sidx0 = g * 32 + ((m ^ g) << 2);
    const int sidx1 = sidx0 ^ 16;

    float xm1 = 0.f, xm2 = 0.f, ym1 = 0.f, ym2 = 0.f;

    // ---- prologue: prefetch iteration 0 (jt = -WARM) into buffer 0
    {
        #pragma unroll
        for (int sub = 0; sub < 2; ++sub) {
            #pragma unroll
            for (int it = 0; it < 8; ++it) {
                int p = slotbase + it * 1024 + (-WARM) + 32 * sub;
                uint32_t d = ringbase + (uint32_t)sub * SUBBYTES
                           + (uint32_t)(it << 9) + ((it & 1) ? off1 : off0);
                cp_async16(d, xs + (p >= 0 ? p : 0), p >= 0 ? 16 : 0);
            }
        }
        asm volatile("cp.async.commit_group;\n");
    }

    #pragma unroll
    for (int t = 0; t < NT2; ++t) {
        const int  jt   = -WARM + t * JT2;
        const bool emit = (t >= 1);           // t=0 is pure warm-up (jt=-64)
        float* buf = &tile[w][t & 1][0][0][0];
        const int lq = lane & 7;

        // ---- prefetch iteration t+1 into the other buffer, then wait for
        //      tile t (lead = one full iteration)
        if (t + 1 < NT2) {
            const int jn = jt + JT2;
            const uint32_t dbase = ringbase + (uint32_t)((t + 1) & 1) * BUFBYTES;
            #pragma unroll
            for (int sub = 0; sub < 2; ++sub) {
                #pragma unroll
                for (int it = 0; it < 8; ++it) {
                    int p = slotbase + it * 1024 + jn + 32 * sub;
                    uint32_t d = dbase + (uint32_t)sub * SUBBYTES
                               + (uint32_t)(it << 9) + ((it & 1) ? off1 : off0);
                    cp_async16(d, xs + (p >= 0 ? p : 0), p >= 0 ? 16 : 0);
                }
            }
            asm volatile("cp.async.commit_group;\n");
            asm volatile("cp.async.wait_group 1;\n");   // tile t landed
        } else {
            asm volatile("cp.async.wait_group 0;\n");
        }
        __syncwarp();

        // ---- advance this lane's chunk 64 samples (2 subtiles, serial chain)
        #pragma unroll
        for (int sub = 0; sub < 2; ++sub) {
            float* row = buf + sub * 1024 + lane * 32;
            #pragma unroll
            for (int jj = 0; jj < 32; jj += 4) {
                const int colq = ((jj >> 2) ^ lq) << 2;
                float4 xv = *reinterpret_cast<float4*>(&row[colq]);

                float t0 = fmaf(b2, xm2, fmaf(b1, xm1, b0 * xv.x));
                float y0 = fmaf(na2, ym2, fmaf(na1, ym1, t0));
                float t1 = fmaf(b2, xm1, fmaf(b1, xv.x, b0 * xv.y));
                float y1 = fmaf(na2, ym1, fmaf(na1, y0, t1));
                float t2 = fmaf(b2, xv.x, fmaf(b1, xv.y, b0 * xv.z));
                float y2 = fmaf(na2, y0, fmaf(na1, y1, t2));
                float t3 = fmaf(b2, xv.y, fmaf(b1, xv.z, b0 * xv.w));
                float y3 = fmaf(na2, y1, fmaf(na1, y2, t3));

                xm2 = xv.z; xm1 = xv.w;
                ym2 = y2;   ym1 = y3;

                if (emit)
                    *reinterpret_cast<float4*>(&row[colq]) =
                        make_float4(y0, y1, y2, y3);
            }
        }
        __syncwarp();

        // ---- coalesced store of both computed subtiles (swizzled SMEM read)
        if (emit) {
            #pragma unroll
            for (int sub = 0; sub < 2; ++sub) {
                const float* sbuf = buf + sub * 1024;
                #pragma unroll
                for (int it = 0; it < 8; ++it) {
                    int p = slotbase + it * 1024 + jt + 32 * sub;
                    const int si = it * 128 + ((it & 1) ? sidx1 : sidx0);
                    *reinterpret_cast<float4*>(ys + p) =
                        *reinterpret_cast<const float4*>(sbuf + si);
                }
            }
        }
        __syncwarp();
    }
}

extern "C" void kernel_launch(void* const* d_in, const int* in_sizes, int n_in,
                              void* d_out, int out_size)
{
    const float* x = (const float*)d_in[0];
    float*       y = (float*)d_out;

    const int total = in_sizes[0];
    const int nseq  = total / T_LEN;          // 256 for the given shapes

    const double w0    = 2.0 * M_PI * (700.0 / 16000.0);
    const double cw    = cos(w0);
    const double sw    = sin(w0);
    const double q     = 0.70710678;
    const double alpha = sw / (2.0 * q);
    const double a0    = 1.0 + alpha;

    const float b0 = (float)(((1.0 + cw) / 2.0) / a0);
    const float b1 = (float)((-(1.0 + cw)) / a0);
    const float b2 = b0;
    const float a1 = (float)((-2.0 * cw) / a0);
    const float a2 = (float)((1.0 - alpha) / a0);

    const int warps_total = nseq * 8;                  // 8 warps per sequence
    const int grid        = warps_total / BLOCK_WARPS; // 1024 blocks
    biquad_hp_kernel<<<grid, BLOCK_WARPS * 32>>>(x, y, b0, b1, b2, -a1, -a2);
}